// round 9
// baseline (speedup 1.0000x reference)
#include <cuda_runtime.h>
#include <cstdint>

#define D        128
#define DH       32
#define NKP      (D / 2)            // 64 k-pairs
#define P_SEG    16384
#define SEG_PER_BLOCK 16
#define NBLOCKS  (P_SEG / SEG_PER_BLOCK)
#define THREADS  256
#define TILE_M   128
#define KC       32                 // floats per staged chunk (16 k-pairs)
#define KPC      (KC / 2)
#define NCHUNK   (D / KC)           // 4
#define XROW_ULL 17                 // 8B units per staged row (odd -> conflict-free)

__device__ int g_seg_start[P_SEG + 1];

typedef unsigned long long ull;

__device__ __forceinline__ ull pack2(float lo, float hi) {
    ull r;
    asm("mov.b64 %0, {%1, %2};" : "=l"(r) : "f"(lo), "f"(hi));
    return r;
}
__device__ __forceinline__ void unpack2(ull v, float& lo, float& hi) {
    asm("mov.b64 {%0, %1}, %2;" : "=f"(lo), "=f"(hi) : "l"(v));
}
// Packed dual-fp32 FMA (FFMA2) — 2x fp32 MAC throughput on sm_103a
__device__ __forceinline__ ull fma2(ull a, ull b, ull c) {
    ull d;
    asm("fma.rn.f32x2 %0, %1, %2, %3;" : "=l"(d) : "l"(a), "l"(b), "l"(c));
    return d;
}
// Single-instruction tanh (MUFU-class). Abs err ~1e-5 -> pooled err << 1e-3.
__device__ __forceinline__ float tanh_fast(float x) {
    float y;
    asm("tanh.approx.f32 %0, %1;" : "=f"(y) : "f"(x));
    return y;
}

// Kernel 1: segment boundaries via binary search over sorted person_ids.
__global__ void seg_bounds_kernel(const int* __restrict__ pids, int n) {
    int p = blockIdx.x * blockDim.x + threadIdx.x;
    if (p > P_SEG) return;
    int lo = 0, hi = n;
    while (lo < hi) {
        int mid = (lo + hi) >> 1;
        if (pids[mid] < p) lo = mid + 1; else hi = mid;
    }
    g_seg_start[p] = lo;
}

// Prefetch one 128-row x 32-float chunk into registers (4 float4 / thread).
__device__ __forceinline__ void ldg_chunk(const float* __restrict__ x,
                                          int tbase, int k0, int rend, int tid,
                                          float4* buf) {
    #pragma unroll
    for (int i = 0; i < 4; ++i) {
        int idx = tid + THREADS * i;
        int row = idx >> 3;          // 0..127
        int kq  = idx & 7;           // float4 within the 32-float chunk
        int r   = tbase + row;
        if (r < rend)
            buf[i] = *(const float4*)(x + r * D + k0 + kq * 4);
        else
            buf[i] = make_float4(0.f, 0.f, 0.f, 0.f);
    }
}

// Kernel 2: fully fused single-HBM-pass scores + softmax + pooling.
// One block owns 16 contiguous segments. Per tile: score GEMM (smem-staged),
// exp, then immediate unnormalized pooling accumulation (rows re-read via
// L2-hot LDG) into persistent per-segment shared accumulators. Final divide
// by the segment denominator at block end.
__global__ __launch_bounds__(THREADS, 3)
void pool_kernel(const float* __restrict__ x, const int* __restrict__ pids,
                 const float* __restrict__ W1, const float* __restrict__ b1,
                 const float* __restrict__ W2, const float* __restrict__ b2,
                 float* __restrict__ out, int has_pids) {
    extern __shared__ float dynsm[];
    ull*   sX    = (ull*)dynsm;                      // [TILE_M][17] k-pair rows
    ull*   sWp   = sX + TILE_M * XROW_ULL;           // [64][32] {W[2k][h],W[2k+1][h]}
    float* sSc   = (float*)(sWp + NKP * DH);         // [4][TILE_M] per-hg partials
    float* sE    = sSc + 4 * TILE_M;                 // [TILE_M] e per row
    float* sPool = sE + TILE_M;                      // [16][128] unnorm pooled
    __shared__ float sW2[DH];
    __shared__ float sB1[DH];
    __shared__ int   sStart[SEG_PER_BLOCK + 1];
    __shared__ float sDen[SEG_PER_BLOCK];
    __shared__ int   sSeg[TILE_M];

    const int tid  = threadIdx.x;
    const int tx   = tid & 31;     // lane
    const int ty   = tid >> 5;     // warp id
    const int hg   = ty & 3;       // hidden group: hidden [hg*8, hg*8+8)
    const int rg   = ty >> 2;      // row group: rows [rg*64, rg*64+64)
    const int seg0 = blockIdx.x * SEG_PER_BLOCK;

    if (tid <= SEG_PER_BLOCK) sStart[tid] = g_seg_start[seg0 + tid];
    if (tid < DH) { sW2[tid] = W2[tid]; sB1[tid] = b1[tid]; }
    if (tid < SEG_PER_BLOCK) sDen[tid] = 0.f;
    for (int i = tid; i < NKP * DH; i += THREADS) {
        int kp = i >> 5, h = i & 31;
        sWp[i] = pack2(W1[(2 * kp) * DH + h], W1[(2 * kp + 1) * DH + h]);
    }
    for (int i = tid; i < SEG_PER_BLOCK * D; i += THREADS) sPool[i] = 0.f;
    const float b2v = b2[0];
    __syncthreads();

    const int rbeg = sStart[0], rend = sStart[SEG_PER_BLOCK];
    const int nTiles = (rend - rbeg + TILE_M - 1) / TILE_M;

    float4 buf[4];
    if (nTiles > 0) ldg_chunk(x, rbeg, 0, rend, tid, buf);

    const int row0 = rg * 64 + tx;   // this thread's rows: row0, row0+32

    for (int t = 0; t < nTiles; ++t) {
        const int tbase = rbeg + t * TILE_M;
        ull acc[2][8];
        #pragma unroll
        for (int j = 0; j < 2; ++j)
            #pragma unroll
            for (int jh = 0; jh < 8; ++jh) acc[j][jh] = 0ULL;

        for (int c = 0; c < NCHUNK; ++c) {
            __syncthreads();   // previous compute done reading sX
            // stage chunk c (straight copy, no transpose): float2 = 8B stores
            #pragma unroll
            for (int i = 0; i < 4; ++i) {
                int idx = tid + THREADS * i;
                int row = idx >> 3;
                int kq  = idx & 7;
                float2* dst = (float2*)(sX + row * XROW_ULL + kq * 2);
                dst[0] = make_float2(buf[i].x, buf[i].y);
                dst[1] = make_float2(buf[i].z, buf[i].w);
            }
            __syncthreads();
            // prefetch next chunk (next k-chunk, or next tile's chunk 0)
            int nc = c + 1, nb = tbase;
            if (nc == NCHUNK) { nc = 0; nb += TILE_M; }
            if (nb < rend) ldg_chunk(x, nb, nc * KC, rend, tid, buf);

            // compute: 16 k-pair steps x 16 fma2 per thread
            const int kp0 = c * KPC;
            #pragma unroll 8
            for (int kk = 0; kk < KPC; ++kk) {
                ull xp0 = sX[row0 * XROW_ULL + kk];
                ull xp1 = sX[(row0 + 32) * XROW_ULL + kk];
                const ulonglong2* wr =
                    (const ulonglong2*)(sWp + (kp0 + kk) * DH + hg * 8);
                ulonglong2 wa = wr[0], wb = wr[1], wc = wr[2], wd = wr[3];
                acc[0][0] = fma2(xp0, wa.x, acc[0][0]);
                acc[0][1] = fma2(xp0, wa.y, acc[0][1]);
                acc[0][2] = fma2(xp0, wb.x, acc[0][2]);
                acc[0][3] = fma2(xp0, wb.y, acc[0][3]);
                acc[0][4] = fma2(xp0, wc.x, acc[0][4]);
                acc[0][5] = fma2(xp0, wc.y, acc[0][5]);
                acc[0][6] = fma2(xp0, wd.x, acc[0][6]);
                acc[0][7] = fma2(xp0, wd.y, acc[0][7]);
                acc[1][0] = fma2(xp1, wa.x, acc[1][0]);
                acc[1][1] = fma2(xp1, wa.y, acc[1][1]);
                acc[1][2] = fma2(xp1, wb.x, acc[1][2]);
                acc[1][3] = fma2(xp1, wb.y, acc[1][3]);
                acc[1][4] = fma2(xp1, wc.x, acc[1][4]);
                acc[1][5] = fma2(xp1, wc.y, acc[1][5]);
                acc[1][6] = fma2(xp1, wd.x, acc[1][6]);
                acc[1][7] = fma2(xp1, wd.y, acc[1][7]);
            }
        }

        // partial scores: tanh + W2 over this thread's 8 hidden, per row.
        #pragma unroll
        for (int j = 0; j < 2; ++j) {
            float s = 0.f;
            #pragma unroll
            for (int jh = 0; jh < 8; ++jh) {
                int h = hg * 8 + jh;
                float lo, hi;
                unpack2(acc[j][jh], lo, hi);
                s += tanh_fast(lo + hi + sB1[h]) * sW2[h];
            }
            sSc[hg * TILE_M + row0 + 32 * j] = s;   // plain store, no atomics
        }
        __syncthreads();

        // finalize: one thread per row. |score| <= ~6 analytically, exp safe.
        if (tid < TILE_M) {
            int row = tbase + tid;
            if (row < rend) {
                float sc = sSc[tid] + sSc[TILE_M + tid] +
                           sSc[2 * TILE_M + tid] + sSc[3 * TILE_M + tid] + b2v;
                float e = __expf(sc);
                int sg = pids[row] - seg0;
                sE[tid]   = e;
                sSeg[tid] = sg;
                atomicAdd(&sDen[sg], e);
            }
        }
        __syncthreads();

        // ---- inline pooling of this tile (rows are L2-hot) ----
        {
            const int nrows = min(TILE_M, rend - tbase);
            const int r0 = ty * 16;
            const int r1 = min(r0 + 16, nrows);
            if (r0 < r1) {
                int cur = sSeg[r0];
                float4 a4 = make_float4(0.f, 0.f, 0.f, 0.f);
                #pragma unroll 4
                for (int r = r0; r < r1; ++r) {
                    int sg = sSeg[r];
                    if (sg != cur) {
                        float* p = sPool + cur * D + tx * 4;
                        atomicAdd(p + 0, a4.x); atomicAdd(p + 1, a4.y);
                        atomicAdd(p + 2, a4.z); atomicAdd(p + 3, a4.w);
                        a4 = make_float4(0.f, 0.f, 0.f, 0.f);
                        cur = sg;
                    }
                    float e = sE[r];
                    float4 xv = __ldg((const float4*)(x + (tbase + r) * D + tx * 4));
                    a4.x = fmaf(e, xv.x, a4.x);
                    a4.y = fmaf(e, xv.y, a4.y);
                    a4.z = fmaf(e, xv.z, a4.z);
                    a4.w = fmaf(e, xv.w, a4.w);
                }
                float* p = sPool + cur * D + tx * 4;
                atomicAdd(p + 0, a4.x); atomicAdd(p + 1, a4.y);
                atomicAdd(p + 2, a4.z); atomicAdd(p + 3, a4.w);
            }
        }
        // next loop iteration's first __syncthreads() orders pooling
        // before sX restaging; sE/sSeg rewritten only after 4 more syncs.
    }
    __syncthreads();

    // ---- epilogue: normalize + write out; warp ty -> segments ty, ty+8 ----
    for (int s = ty; s < SEG_PER_BLOCK; s += 8) {
        const float den  = sDen[s];
        const float dinv = den > 0.f ? 1.f / den : 0.f;
        float4 v = *(float4*)(sPool + s * D + tx * 4);
        v.x *= dinv; v.y *= dinv; v.z *= dinv; v.w *= dinv;
        *(float4*)(out + (seg0 + s) * D + tx * 4) = v;
    }

    // ---- pooled_pids tail (arange), if the output buffer includes it ----
    if (has_pids && tid < SEG_PER_BLOCK) {
        out[P_SEG * D + seg0 + tid] = (float)(seg0 + tid);
    }
}

extern "C" void kernel_launch(void* const* d_in, const int* in_sizes, int n_in,
                              void* d_out, int out_size) {
    const float* x   = (const float*)d_in[0];
    const int*   pid = (const int*)d_in[1];
    const float* W1  = (const float*)d_in[2];
    const float* b1  = (const float*)d_in[3];
    const float* W2  = (const float*)d_in[4];
    const float* b2  = (const float*)d_in[5];
    const int n = in_sizes[1];
    const int has_pids = (out_size >= P_SEG * D + P_SEG) ? 1 : 0;

    seg_bounds_kernel<<<(P_SEG + 1 + 255) / 256, 256>>>(pid, n);

    const int smem_bytes = TILE_M * XROW_ULL * 8      // sX
                         + NKP * DH * 8               // sWp
                         + 4 * TILE_M * 4             // sSc
                         + TILE_M * 4                 // sE
                         + SEG_PER_BLOCK * D * 4;     // sPool
    cudaFuncSetAttribute((const void*)pool_kernel,
                         cudaFuncAttributeMaxDynamicSharedMemorySize,
                         smem_bytes);
    pool_kernel<<<NBLOCKS, THREADS, smem_bytes>>>(
        x, pid, W1, b1, W2, b2, (float*)d_out, has_pids);
}

// round 11
// speedup vs baseline: 1.0826x; 1.0826x over previous
#include <cuda_runtime.h>
#include <cstdint>

#define D        128
#define DH       32
#define NKP      (D / 2)            // 64 k-pairs
#define P_SEG    16384
#define SEG_PER_BLOCK 16
#define NBLOCKS  (P_SEG / SEG_PER_BLOCK)
#define THREADS  256
#define TILE_M   128
#define KC       32                 // floats per staged chunk (16 k-pairs)
#define KPC      (KC / 2)           // 16 ull per chunk slice
#define NCHUNK   (D / KC)           // 4
#define XROW_ULL 65                 // ull per full row (64 pairs + 1 pad; odd -> conflict-free)

__device__ int g_seg_start[P_SEG + 1];

typedef unsigned long long ull;

__device__ __forceinline__ ull pack2(float lo, float hi) {
    ull r;
    asm("mov.b64 %0, {%1, %2};" : "=l"(r) : "f"(lo), "f"(hi));
    return r;
}
__device__ __forceinline__ void unpack2(ull v, float& lo, float& hi) {
    asm("mov.b64 {%0, %1}, %2;" : "=f"(lo), "=f"(hi) : "l"(v));
}
// Packed dual-fp32 FMA (FFMA2) — 2x fp32 MAC throughput on sm_103a
__device__ __forceinline__ ull fma2(ull a, ull b, ull c) {
    ull d;
    asm("fma.rn.f32x2 %0, %1, %2, %3;" : "=l"(d) : "l"(a), "l"(b), "l"(c));
    return d;
}
// Single-instruction tanh (MUFU-class). Abs err ~1e-5 -> pooled err << 1e-3.
__device__ __forceinline__ float tanh_fast(float x) {
    float y;
    asm("tanh.approx.f32 %0, %1;" : "=f"(y) : "f"(x));
    return y;
}

// Kernel 1: segment boundaries via binary search over sorted person_ids.
__global__ void seg_bounds_kernel(const int* __restrict__ pids, int n) {
    int p = blockIdx.x * blockDim.x + threadIdx.x;
    if (p > P_SEG) return;
    int lo = 0, hi = n;
    while (lo < hi) {
        int mid = (lo + hi) >> 1;
        if (pids[mid] < p) lo = mid + 1; else hi = mid;
    }
    g_seg_start[p] = lo;
}

// Prefetch one 128-row x 32-float chunk into registers (4 float4 / thread).
__device__ __forceinline__ void ldg_chunk(const float* __restrict__ x,
                                          int tbase, int k0, int rend, int tid,
                                          float4* buf) {
    #pragma unroll
    for (int i = 0; i < 4; ++i) {
        int idx = tid + THREADS * i;
        int row = idx >> 3;          // 0..127
        int kq  = idx & 7;           // float4 within the 32-float chunk
        int r   = tbase + row;
        if (r < rend)
            buf[i] = *(const float4*)(x + r * D + k0 + kq * 4);
        else
            buf[i] = make_float4(0.f, 0.f, 0.f, 0.f);
    }
}

// Kernel 2: single-HBM-pass fused scores + softmax + pooling.
// The full 128-row tile stays RESIDENT in shared (sX[128][65 ull]); chunks
// stream into disjoint slices, the score GEMM reads k-pairs from it, and the
// pooling re-reads rows from the SAME shared buffer (LDS, no second gmem pass).
__global__ __launch_bounds__(THREADS, 2)
void pool_kernel(const float* __restrict__ x, const int* __restrict__ pids,
                 const float* __restrict__ W1, const float* __restrict__ b1,
                 const float* __restrict__ W2, const float* __restrict__ b2,
                 float* __restrict__ out, int has_pids) {
    extern __shared__ float dynsm[];
    ull*   sX    = (ull*)dynsm;                      // [TILE_M][65] full tile, k-pairs
    ull*   sWp   = sX + TILE_M * XROW_ULL;           // [64][32] {W[2k][h],W[2k+1][h]}
    float* sSc   = (float*)(sWp + NKP * DH);         // [4][TILE_M] per-hg partials
    float* sE    = sSc + 4 * TILE_M;                 // [TILE_M] e per row
    float* sPool = sE + TILE_M;                      // [16][128] unnorm pooled
    __shared__ float sW2[DH];
    __shared__ float sB1[DH];
    __shared__ int   sStart[SEG_PER_BLOCK + 1];
    __shared__ float sDen[SEG_PER_BLOCK];
    __shared__ int   sSeg[TILE_M];

    const int tid  = threadIdx.x;
    const int tx   = tid & 31;     // lane
    const int ty   = tid >> 5;     // warp id
    const int hg   = ty & 3;       // hidden group: hidden [hg*8, hg*8+8)
    const int rg   = ty >> 2;      // row group: rows [rg*64, rg*64+64)
    const int seg0 = blockIdx.x * SEG_PER_BLOCK;

    if (tid <= SEG_PER_BLOCK) sStart[tid] = g_seg_start[seg0 + tid];
    if (tid < DH) { sW2[tid] = W2[tid]; sB1[tid] = b1[tid]; }
    if (tid < SEG_PER_BLOCK) sDen[tid] = 0.f;
    for (int i = tid; i < NKP * DH; i += THREADS) {
        int kp = i >> 5, h = i & 31;
        sWp[i] = pack2(W1[(2 * kp) * DH + h], W1[(2 * kp + 1) * DH + h]);
    }
    for (int i = tid; i < SEG_PER_BLOCK * D; i += THREADS) sPool[i] = 0.f;
    const float b2v = b2[0];
    __syncthreads();

    const int rbeg = sStart[0], rend = sStart[SEG_PER_BLOCK];
    const int nTiles = (rend - rbeg + TILE_M - 1) / TILE_M;

    float4 buf[4];
    if (nTiles > 0) ldg_chunk(x, rbeg, 0, rend, tid, buf);

    const int row0 = rg * 64 + tx;   // this thread's rows: row0, row0+32

    for (int t = 0; t < nTiles; ++t) {
        const int tbase = rbeg + t * TILE_M;
        ull acc[2][8];
        #pragma unroll
        for (int j = 0; j < 2; ++j)
            #pragma unroll
            for (int jh = 0; jh < 8; ++jh) acc[j][jh] = 0ULL;

        for (int c = 0; c < NCHUNK; ++c) {
            // stage chunk c into its disjoint slice [c*KPC, c*KPC+16) of each row.
            // No pre-barrier needed: this region is not read by any in-flight
            // chunk of this tile, and the previous tile (incl. pooling) is
            // fully ordered behind the pooling barrier.
            #pragma unroll
            for (int i = 0; i < 4; ++i) {
                int idx = tid + THREADS * i;
                int row = idx >> 3;
                int kq  = idx & 7;
                float2* dst = (float2*)(sX + row * XROW_ULL + c * KPC + kq * 2);
                dst[0] = make_float2(buf[i].x, buf[i].y);
                dst[1] = make_float2(buf[i].z, buf[i].w);
            }
            __syncthreads();
            // prefetch next chunk (next k-chunk, or next tile's chunk 0)
            int nc = c + 1, nb = tbase;
            if (nc == NCHUNK) { nc = 0; nb += TILE_M; }
            if (nb < rend) ldg_chunk(x, nb, nc * KC, rend, tid, buf);

            // compute: 16 k-pair steps x 16 fma2 per thread
            const int kp0 = c * KPC;
            #pragma unroll 8
            for (int kk = 0; kk < KPC; ++kk) {
                ull xp0 = sX[row0 * XROW_ULL + kp0 + kk];
                ull xp1 = sX[(row0 + 32) * XROW_ULL + kp0 + kk];
                const ulonglong2* wr =
                    (const ulonglong2*)(sWp + (kp0 + kk) * DH + hg * 8);
                ulonglong2 wa = wr[0], wb = wr[1], wc = wr[2], wd = wr[3];
                acc[0][0] = fma2(xp0, wa.x, acc[0][0]);
                acc[0][1] = fma2(xp0, wa.y, acc[0][1]);
                acc[0][2] = fma2(xp0, wb.x, acc[0][2]);
                acc[0][3] = fma2(xp0, wb.y, acc[0][3]);
                acc[0][4] = fma2(xp0, wc.x, acc[0][4]);
                acc[0][5] = fma2(xp0, wc.y, acc[0][5]);
                acc[0][6] = fma2(xp0, wd.x, acc[0][6]);
                acc[0][7] = fma2(xp0, wd.y, acc[0][7]);
                acc[1][0] = fma2(xp1, wa.x, acc[1][0]);
                acc[1][1] = fma2(xp1, wa.y, acc[1][1]);
                acc[1][2] = fma2(xp1, wb.x, acc[1][2]);
                acc[1][3] = fma2(xp1, wb.y, acc[1][3]);
                acc[1][4] = fma2(xp1, wc.x, acc[1][4]);
                acc[1][5] = fma2(xp1, wc.y, acc[1][5]);
                acc[1][6] = fma2(xp1, wd.x, acc[1][6]);
                acc[1][7] = fma2(xp1, wd.y, acc[1][7]);
            }
        }

        // partial scores: tanh + W2 over this thread's 8 hidden, per row.
        #pragma unroll
        for (int j = 0; j < 2; ++j) {
            float s = 0.f;
            #pragma unroll
            for (int jh = 0; jh < 8; ++jh) {
                int h = hg * 8 + jh;
                float lo, hi;
                unpack2(acc[j][jh], lo, hi);
                s += tanh_fast(lo + hi + sB1[h]) * sW2[h];
            }
            sSc[hg * TILE_M + row0 + 32 * j] = s;   // plain store, no atomics
        }
        __syncthreads();

        // finalize: one thread per row. |score| <= ~6 analytically, exp safe.
        if (tid < TILE_M) {
            int row = tbase + tid;
            if (row < rend) {
                float sc = sSc[tid] + sSc[TILE_M + tid] +
                           sSc[2 * TILE_M + tid] + sSc[3 * TILE_M + tid] + b2v;
                float e = __expf(sc);
                int sg = pids[row] - seg0;
                sE[tid]   = e;
                sSeg[tid] = sg;
                atomicAdd(&sDen[sg], e);
            }
        }
        __syncthreads();

        // ---- inline pooling of this tile from RESIDENT shared rows ----
        {
            const int nrows = min(TILE_M, rend - tbase);
            const int r0 = ty * 16;
            const int r1 = min(r0 + 16, nrows);
            if (r0 < r1) {
                int cur = sSeg[r0];
                float4 a4 = make_float4(0.f, 0.f, 0.f, 0.f);
                #pragma unroll 4
                for (int r = r0; r < r1; ++r) {
                    int sg = sSeg[r];
                    if (sg != cur) {
                        float* p = sPool + cur * D + tx * 4;
                        atomicAdd(p + 0, a4.x); atomicAdd(p + 1, a4.y);
                        atomicAdd(p + 2, a4.z); atomicAdd(p + 3, a4.w);
                        a4 = make_float4(0.f, 0.f, 0.f, 0.f);
                        cur = sg;
                    }
                    float e = sE[r];
                    // contiguous per-row LDS (conflict-free)
                    ull w0 = sX[r * XROW_ULL + tx * 2];
                    ull w1 = sX[r * XROW_ULL + tx * 2 + 1];
                    float x0, x1, x2, x3;
                    unpack2(w0, x0, x1);
                    unpack2(w1, x2, x3);
                    a4.x = fmaf(e, x0, a4.x);
                    a4.y = fmaf(e, x1, a4.y);
                    a4.z = fmaf(e, x2, a4.z);
                    a4.w = fmaf(e, x3, a4.w);
                }
                float* p = sPool + cur * D + tx * 4;
                atomicAdd(p + 0, a4.x); atomicAdd(p + 1, a4.y);
                atomicAdd(p + 2, a4.z); atomicAdd(p + 3, a4.w);
            }
        }
        __syncthreads();   // pooling done before tile t+1 overwrites sX
    }

    // ---- epilogue: normalize + write out; warp ty -> segments ty, ty+8 ----
    for (int s = ty; s < SEG_PER_BLOCK; s += 8) {
        const float den  = sDen[s];
        const float dinv = den > 0.f ? 1.f / den : 0.f;
        float4 v = *(float4*)(sPool + s * D + tx * 4);
        v.x *= dinv; v.y *= dinv; v.z *= dinv; v.w *= dinv;
        *(float4*)(out + (seg0 + s) * D + tx * 4) = v;
    }

    // ---- pooled_pids tail (arange), if the output buffer includes it ----
    if (has_pids && tid < SEG_PER_BLOCK) {
        out[P_SEG * D + seg0 + tid] = (float)(seg0 + tid);
    }
}

extern "C" void kernel_launch(void* const* d_in, const int* in_sizes, int n_in,
                              void* d_out, int out_size) {
    const float* x   = (const float*)d_in[0];
    const int*   pid = (const int*)d_in[1];
    const float* W1  = (const float*)d_in[2];
    const float* b1  = (const float*)d_in[3];
    const float* W2  = (const float*)d_in[4];
    const float* b2  = (const float*)d_in[5];
    const int n = in_sizes[1];
    const int has_pids = (out_size >= P_SEG * D + P_SEG) ? 1 : 0;

    seg_bounds_kernel<<<(P_SEG + 1 + 255) / 256, 256>>>(pid, n);

    const int smem_bytes = TILE_M * XROW_ULL * 8      // sX full tile
                         + NKP * DH * 8               // sWp
                         + 4 * TILE_M * 4             // sSc
                         + TILE_M * 4                 // sE
                         + SEG_PER_BLOCK * D * 4;     // sPool
    cudaFuncSetAttribute((const void*)pool_kernel,
                         cudaFuncAttributeMaxDynamicSharedMemorySize,
                         smem_bytes);
    pool_kernel<<<NBLOCKS, THREADS, smem_bytes>>>(
        x, pid, W1, b1, W2, b2, (float*)d_out, has_pids);
}